// round 1
// baseline (speedup 1.0000x reference)
#include <cuda_runtime.h>

// ---------------- scratch (static device globals; no allocations) ----------
__device__ float g_h1[32u*64*64*64];     // conv1 out, NCHW [32,64,64,64]
__device__ float g_f [32u*32*32*128];    // conv2 out, NHWC [32,32,32,128]
__device__ float g_q [32u*4*1024*16];    // [b,head,y,x,d]
__device__ float g_k [32u*4*1024*16];
__device__ float g_v [32u*4*1024*16];
__device__ float g_o [32u*1024*64];      // [b,y,x, head*16+d]

// ---------------- conv1 + relu + maxpool2 ----------------------------------
// x [32,3,128,128] -> g_h1 [32,64,64,64]
__global__ __launch_bounds__(256) void conv1_kernel(const float* __restrict__ x,
                                                    const float* __restrict__ w,
                                                    const float* __restrict__ bias) {
    __shared__ float s_in[3*34*34];
    __shared__ float s_w[64*27];
    __shared__ float s_b[64];
    int b  = blockIdx.y;
    int tY = blockIdx.x >> 2, tX = blockIdx.x & 3;
    int Py0 = tY*16, Px0 = tX*16;
    int tid = threadIdx.x;

    for (int i = tid; i < 64*27; i += 256) s_w[i] = w[i];
    if (tid < 64) s_b[tid] = bias[tid];

    const float* xb = x + (size_t)b*3*128*128;
    for (int i = tid; i < 3*34*34; i += 256) {
        int ci = i / 1156, rem2 = i % 1156;
        int ly = rem2 / 34, lx = rem2 % 34;
        int gy = 2*Py0 - 1 + ly, gx = 2*Px0 - 1 + lx;
        float v = 0.f;
        if (gy >= 0 && gy < 128 && gx >= 0 && gx < 128)
            v = xb[(size_t)ci*16384 + gy*128 + gx];
        s_in[i] = v;
    }
    __syncthreads();

    int ty = tid >> 4, tx = tid & 15;
    float win[3][16];
    #pragma unroll
    for (int ci = 0; ci < 3; ci++)
        #pragma unroll
        for (int r = 0; r < 4; r++)
            #pragma unroll
            for (int c = 0; c < 4; c++)
                win[ci][r*4+c] = s_in[ci*1156 + (2*ty + r)*34 + (2*tx + c)];

    int Y = Py0 + ty, X = Px0 + tx;
    float* outp = g_h1 + (size_t)b*64*4096 + (size_t)Y*64 + X;
    #pragma unroll 1
    for (int co = 0; co < 64; co++) {
        float a0=0.f, a1=0.f, a2=0.f, a3=0.f;
        const float* wp = &s_w[co*27];
        #pragma unroll
        for (int ci = 0; ci < 3; ci++)
            #pragma unroll
            for (int k = 0; k < 9; k++) {
                int ky = k/3, kx = k%3;
                float wv = wp[ci*9+k];
                a0 = fmaf(win[ci][ ky   *4 + kx    ], wv, a0);
                a1 = fmaf(win[ci][ ky   *4 + kx + 1], wv, a1);
                a2 = fmaf(win[ci][(ky+1)*4 + kx    ], wv, a2);
                a3 = fmaf(win[ci][(ky+1)*4 + kx + 1], wv, a3);
            }
        float m = fmaxf(fmaxf(a0,a1), fmaxf(a2,a3));
        outp[(size_t)co*4096] = fmaxf(m + s_b[co], 0.f);
    }
}

// ---------------- conv2 + relu + maxpool2 ----------------------------------
// g_h1 [32,64,64,64] -> g_f NHWC [32,32,32,128]
// block: 8x8 pooled tile x 32 co (blockIdx.z picks co-group of 32)
// thread: (pos, g) = 1 pooled position x 8 co
__global__ __launch_bounds__(256) void conv2_kernel(const float* __restrict__ w2,
                                                    const float* __restrict__ b2) {
    extern __shared__ float smem[];
    float* s_in = smem;          // 64*324 = 20736 floats
    float* s_w  = smem + 20736;  // 576*36 = 20736 floats (row stride 36, 16B-alignable)

    int b   = blockIdx.y;
    int cog = blockIdx.z;
    int tY  = blockIdx.x >> 2, tX = blockIdx.x & 3;
    int Py0 = tY*8, Px0 = tX*8;
    int tid = threadIdx.x;

    const float* hb = g_h1 + (size_t)b*64*4096;
    for (int i = tid; i < 64*324; i += 256) {
        int ci = i / 324, rem2 = i % 324;
        int ly = rem2 / 18, lx = rem2 % 18;
        int gy = 2*Py0 - 1 + ly, gx = 2*Px0 - 1 + lx;
        float v = 0.f;
        if (gy >= 0 && gy < 64 && gx >= 0 && gx < 64)
            v = hb[(size_t)ci*4096 + gy*64 + gx];
        s_in[i] = v;
    }
    const float* wg = w2 + (size_t)cog*18432;   // 32 co x 576
    for (int i = tid; i < 18432; i += 256) {
        int col = i / 576, rem2 = i % 576;      // rem2 = ci*9+k
        s_w[rem2*36 + col] = wg[i];
    }
    __syncthreads();

    int pos = tid >> 2, g = tid & 3;
    int ty = pos >> 3, tx = pos & 7;

    float acc[8][4];
    #pragma unroll
    for (int j = 0; j < 8; j++)
        #pragma unroll
        for (int e = 0; e < 4; e++) acc[j][e] = 0.f;

    #pragma unroll 1
    for (int ci = 0; ci < 64; ci++) {
        float win[16];
        #pragma unroll
        for (int r = 0; r < 4; r++)
            #pragma unroll
            for (int c = 0; c < 4; c++)
                win[r*4+c] = s_in[ci*324 + (2*ty + r)*18 + (2*tx + c)];
        const float* wp = s_w + ci*324 + g*8;   // ci*9*36
        #pragma unroll
        for (int k = 0; k < 9; k++) {
            int ky = k/3, kx = k%3;
            float4 w0 = *reinterpret_cast<const float4*>(wp + k*36);
            float4 w1 = *reinterpret_cast<const float4*>(wp + k*36 + 4);
            float wv[8] = {w0.x,w0.y,w0.z,w0.w,w1.x,w1.y,w1.z,w1.w};
            #pragma unroll
            for (int j = 0; j < 8; j++) {
                acc[j][0] = fmaf(win[ ky   *4 + kx    ], wv[j], acc[j][0]);
                acc[j][1] = fmaf(win[ ky   *4 + kx + 1], wv[j], acc[j][1]);
                acc[j][2] = fmaf(win[(ky+1)*4 + kx    ], wv[j], acc[j][2]);
                acc[j][3] = fmaf(win[(ky+1)*4 + kx + 1], wv[j], acc[j][3]);
            }
        }
    }

    int Y = Py0 + ty, X = Px0 + tx;
    int co0 = cog*32 + g*8;
    float vals[8];
    #pragma unroll
    for (int j = 0; j < 8; j++) {
        float m = fmaxf(fmaxf(acc[j][0],acc[j][1]), fmaxf(acc[j][2],acc[j][3]));
        vals[j] = fmaxf(m + __ldg(&b2[co0+j]), 0.f);
    }
    float* fp = g_f + (((size_t)b*32 + Y)*32 + X)*128 + co0;
    *reinterpret_cast<float4*>(fp)     = make_float4(vals[0],vals[1],vals[2],vals[3]);
    *reinterpret_cast<float4*>(fp + 4) = make_float4(vals[4],vals[5],vals[6],vals[7]);
}

// ---------------- fused QKV projection -------------------------------------
// g_f [32768,128] x (q|k|v)_w [64,128] -> g_q/g_k/g_v; q pre-scaled by 0.25
__global__ __launch_bounds__(256) void qkv_kernel(
    const float* __restrict__ qw, const float* __restrict__ qb,
    const float* __restrict__ kw, const float* __restrict__ kb,
    const float* __restrict__ vw, const float* __restrict__ vb) {
    extern __shared__ float smem[];
    float* s_f = smem;          // 32*128 = 4096
    float* s_w = smem + 4096;   // 128*193 = 24704 (pad to kill store conflicts)
    int tid = threadIdx.x;
    int t0  = blockIdx.x * 32;

    for (int i = tid; i < 4096; i += 256) s_f[i] = g_f[(size_t)t0*128 + i];
    for (int i = tid; i < 24576; i += 256) {
        int o = i >> 7, kk = i & 127;
        float v;
        if (o < 64)       v = qw[i];
        else if (o < 128) v = kw[i - 8192];
        else              v = vw[i - 16384];
        s_w[kk*193 + o] = v;
    }
    __syncthreads();

    int og = tid & 31, tg = tid >> 5;   // warp: fixed 4-token group, 32 out-groups
    float acc[4][6];
    #pragma unroll
    for (int a = 0; a < 4; a++)
        #pragma unroll
        for (int j = 0; j < 6; j++) acc[a][j] = 0.f;

    #pragma unroll 2
    for (int kk = 0; kk < 128; kk++) {
        float fv[4];
        #pragma unroll
        for (int a = 0; a < 4; a++) fv[a] = s_f[(tg*4+a)*128 + kk];
        const float* wrow = s_w + kk*193 + og*6;
        #pragma unroll
        for (int j = 0; j < 6; j++) {
            float wv = wrow[j];
            #pragma unroll
            for (int a = 0; a < 4; a++) acc[a][j] = fmaf(fv[a], wv, acc[a][j]);
        }
    }

    #pragma unroll
    for (int a = 0; a < 4; a++) {
        int t = t0 + tg*4 + a;
        int bidx = t >> 10, rem = t & 1023;
        #pragma unroll
        for (int j = 0; j < 6; j++) {
            int o = og*6 + j;
            float val = acc[a][j];
            if (o < 64) {
                val = (val + __ldg(&qb[o])) * 0.25f;   // DH^-0.5 = 0.25
                int head = o >> 4, d = o & 15;
                g_q[((size_t)(bidx*4 + head)*1024 + rem)*16 + d] = val;
            } else if (o < 128) {
                int c = o - 64; val += __ldg(&kb[c]);
                int head = c >> 4, d = c & 15;
                g_k[((size_t)(bidx*4 + head)*1024 + rem)*16 + d] = val;
            } else {
                int c = o - 128; val += __ldg(&vb[c]);
                int head = c >> 4, d = c & 15;
                g_v[((size_t)(bidx*4 + head)*1024 + rem)*16 + d] = val;
            }
        }
    }
}

// ---------------- axial row attention (along W) -----------------------------
__global__ __launch_bounds__(256) void attn_row_kernel(const float* __restrict__ rel_w) {
    int line = blockIdx.x;              // bh*32 + y
    int y = line & 31, bh = line >> 5;
    int head = bh & 3, b = bh >> 2;
    __shared__ float qs[512], ks[512], vs[512], ps[1024];
    int tid = threadIdx.x;
    size_t base = ((size_t)bh*32 + y)*512;
    for (int i = tid; i < 512; i += 256) {
        qs[i] = g_q[base + i];
        ks[i] = g_k[base + i];
        vs[i] = g_v[base + i];
    }
    __syncthreads();
    for (int e = tid; e < 1024; e += 256) {
        int i = e >> 5, j = e & 31;
        float s = 0.f;
        #pragma unroll
        for (int d = 0; d < 16; d++) s = fmaf(qs[i*16+d], ks[j*16+d], s);
        ps[e] = s + __ldg(&rel_w[head*63 + i - j + 31]);
    }
    __syncthreads();
    int lane = tid & 31, w = tid >> 5;
    #pragma unroll
    for (int r = 0; r < 4; r++) {
        int i = w*4 + r;
        float xv = ps[i*32 + lane];
        float m = xv;
        #pragma unroll
        for (int off = 16; off; off >>= 1) m = fmaxf(m, __shfl_xor_sync(0xffffffffu, m, off));
        float e2 = __expf(xv - m);
        float ss = e2;
        #pragma unroll
        for (int off = 16; off; off >>= 1) ss += __shfl_xor_sync(0xffffffffu, ss, off);
        ps[i*32 + lane] = e2 / ss;
    }
    __syncthreads();
    for (int e = tid; e < 512; e += 256) {
        int i = e >> 4, d = e & 15;
        float o = 0.f;
        #pragma unroll
        for (int j = 0; j < 32; j++) o = fmaf(ps[i*32+j], vs[j*16+d], o);
        int token = (b*32 + y)*32 + i;
        g_o[(size_t)token*64 + head*16 + d] = o;
    }
}

// ---------------- axial column attention (along H), accumulates into g_o ----
__global__ __launch_bounds__(256) void attn_col_kernel(const float* __restrict__ rel_h) {
    int line = blockIdx.x;              // bh*32 + x
    int xcol = line & 31, bh = line >> 5;
    int head = bh & 3, b = bh >> 2;
    __shared__ float qs[512], ks[512], vs[512], ps[1024];
    int tid = threadIdx.x;
    for (int idx = tid; idx < 512; idx += 256) {
        int i = idx >> 4, d = idx & 15;
        size_t gidx = (((size_t)bh*32 + i)*32 + xcol)*16 + d;
        qs[idx] = g_q[gidx]; ks[idx] = g_k[gidx]; vs[idx] = g_v[gidx];
    }
    __syncthreads();
    for (int e = tid; e < 1024; e += 256) {
        int i = e >> 5, j = e & 31;
        float s = 0.f;
        #pragma unroll
        for (int d = 0; d < 16; d++) s = fmaf(qs[i*16+d], ks[j*16+d], s);
        ps[e] = s + __ldg(&rel_h[head*63 + i - j + 31]);
    }
    __syncthreads();
    int lane = tid & 31, w = tid >> 5;
    #pragma unroll
    for (int r = 0; r < 4; r++) {
        int i = w*4 + r;
        float xv = ps[i*32 + lane];
        float m = xv;
        #pragma unroll
        for (int off = 16; off; off >>= 1) m = fmaxf(m, __shfl_xor_sync(0xffffffffu, m, off));
        float e2 = __expf(xv - m);
        float ss = e2;
        #pragma unroll
        for (int off = 16; off; off >>= 1) ss += __shfl_xor_sync(0xffffffffu, ss, off);
        ps[i*32 + lane] = e2 / ss;
    }
    __syncthreads();
    for (int e = tid; e < 512; e += 256) {
        int i = e >> 4, d = e & 15;
        float o = 0.f;
        #pragma unroll
        for (int j = 0; j < 32; j++) o = fmaf(ps[i*32+j], vs[j*16+d], o);
        int token = (b*32 + i)*32 + xcol;
        float* op = &g_o[(size_t)token*64 + head*16 + d];
        *op += o;    // row kernel ran first on same stream; disjoint writers
    }
}

// ---------------- final: mean-pool + (linear-folded) proj + fc --------------
// pooled = mean(f) + proj_w @ mean(o) + proj_b ; out = pooled @ fc_w^T + fc_b
__global__ __launch_bounds__(256) void reduce_kernel(
    const float* __restrict__ proj_w, const float* __restrict__ proj_b,
    const float* __restrict__ fc_w,   const float* __restrict__ fc_b,
    float* __restrict__ out) {
    int b = blockIdx.x, tid = threadIdx.x;
    __shared__ float s_tmp[256], s_tmpo[256], s_meanf[128], s_meano[64], s_pooled[128];
    const float* fb = g_f + (size_t)b*1024*128;
    int c = tid & 127, half = tid >> 7;
    float acc = 0.f;
    for (int t = half; t < 1024; t += 2) acc += fb[t*128 + c];
    s_tmp[tid] = acc;
    const float* ob = g_o + (size_t)b*1024*64;
    int c2 = tid & 63, grp = tid >> 6;
    float acco = 0.f;
    for (int t = grp; t < 1024; t += 4) acco += ob[t*64 + c2];
    s_tmpo[tid] = acco;
    __syncthreads();
    if (tid < 128) s_meanf[tid] = (s_tmp[tid] + s_tmp[tid+128]) * (1.f/1024.f);
    if (tid < 64)  s_meano[tid] = (s_tmpo[tid] + s_tmpo[tid+64] + s_tmpo[tid+128] + s_tmpo[tid+192]) * (1.f/1024.f);
    __syncthreads();
    if (tid < 128) {
        float v2 = s_meanf[tid] + proj_b[tid];
        #pragma unroll 8
        for (int k2 = 0; k2 < 64; k2++) v2 = fmaf(proj_w[tid*64+k2], s_meano[k2], v2);
        s_pooled[tid] = v2;
    }
    __syncthreads();
    if (tid < 10) {
        float v2 = fc_b[tid];
        #pragma unroll 8
        for (int cc = 0; cc < 128; cc++) v2 = fmaf(fc_w[tid*128+cc], s_pooled[cc], v2);
        out[b*10 + tid] = v2;
    }
}

// ---------------- launch ----------------------------------------------------
extern "C" void kernel_launch(void* const* d_in, const int* in_sizes, int n_in,
                              void* d_out, int out_size) {
    (void)in_sizes; (void)n_in; (void)out_size;
    const float* x       = (const float*)d_in[0];
    const float* conv1_w = (const float*)d_in[1];
    const float* conv1_b = (const float*)d_in[2];
    const float* conv2_w = (const float*)d_in[3];
    const float* conv2_b = (const float*)d_in[4];
    const float* q_w     = (const float*)d_in[5];
    const float* q_b     = (const float*)d_in[6];
    const float* k_w     = (const float*)d_in[7];
    const float* k_b     = (const float*)d_in[8];
    const float* v_w     = (const float*)d_in[9];
    const float* v_b     = (const float*)d_in[10];
    const float* proj_w  = (const float*)d_in[11];
    const float* proj_b  = (const float*)d_in[12];
    const float* rel_h   = (const float*)d_in[13];
    const float* rel_w   = (const float*)d_in[14];
    const float* fc_w    = (const float*)d_in[15];
    const float* fc_b    = (const float*)d_in[16];
    float* out = (float*)d_out;

    cudaFuncSetAttribute(conv2_kernel, cudaFuncAttributeMaxDynamicSharedMemorySize, 2*20736*4);
    cudaFuncSetAttribute(qkv_kernel,   cudaFuncAttributeMaxDynamicSharedMemorySize, (4096+24704)*4);

    conv1_kernel<<<dim3(16,32), 256>>>(x, conv1_w, conv1_b);
    conv2_kernel<<<dim3(16,32,4), 256, 2*20736*4>>>(conv2_w, conv2_b);
    qkv_kernel<<<1024, 256, (4096+24704)*4>>>(q_w, q_b, k_w, k_b, v_w, v_b);
    attn_row_kernel<<<4096, 256>>>(rel_w);
    attn_col_kernel<<<4096, 256>>>(rel_h);
    reduce_kernel<<<32, 256>>>(proj_w, proj_b, fc_w, fc_b, out);
}

// round 4
// speedup vs baseline: 1.7988x; 1.7988x over previous
#include <cuda_runtime.h>
#include <cstdint>

// ---------------- scratch (static device globals; no allocations) ----------
__device__ float g_h1p[32u*64*66*66];    // conv1 out, padded NCHW [32][64][66][66]
__device__ float g_w2f[9*8192];          // conv2 weights, mma-fragment order (tf32-rounded)
__device__ float g_f [32u*32*32*128];    // conv2 out, NHWC [32,32,32,128]
__device__ float g_q [32u*4*1024*16];    // [b,head,y,x,d]
__device__ float g_k [32u*4*1024*16];
__device__ float g_v [32u*4*1024*16];
__device__ float g_o [32u*1024*64];      // [b,y,x, head*16+d]

// ---------------- helpers ----------------------------------------------------
__device__ __forceinline__ uint32_t smem_u32(const void* p) {
    uint32_t a;
    asm("{ .reg .u64 t; cvta.to.shared.u64 t, %1; cvt.u32.u64 %0, t; }"
        : "=r"(a) : "l"(p));
    return a;
}
__device__ __forceinline__ float tf32r(float x) {
    uint32_t u;
    asm("cvt.rna.tf32.f32 %0, %1;" : "=r"(u) : "f"(x));
    return __uint_as_float(u);
}
__device__ __forceinline__ void cpa16(uint32_t d, const void* s) {
    asm volatile("cp.async.cg.shared.global [%0], [%1], 16;" :: "r"(d), "l"(s));
}
__device__ __forceinline__ void cpa8(uint32_t d, const void* s) {
    asm volatile("cp.async.ca.shared.global [%0], [%1], 8;" :: "r"(d), "l"(s));
}
__device__ __forceinline__ void mma16n8k8(float* c, const uint32_t* a, const uint32_t* b) {
    asm volatile("mma.sync.aligned.m16n8k8.row.col.f32.tf32.tf32.f32 "
        "{%0,%1,%2,%3}, {%4,%5,%6,%7}, {%8,%9}, {%0,%1,%2,%3};"
        : "+f"(c[0]), "+f"(c[1]), "+f"(c[2]), "+f"(c[3])
        : "r"(a[0]), "r"(a[1]), "r"(a[2]), "r"(a[3]), "r"(b[0]), "r"(b[1]));
}

// ---------------- border zero for padded NCHW h1 ----------------------------
__global__ __launch_bounds__(256) void zero_border_kernel() {
    int b = blockIdx.x;
    float* hb = g_h1p + (size_t)b * 64 * 4356;
    for (int i = threadIdx.x; i < 16640; i += 256) {
        int co = i / 260, j = i % 260;
        int p, q;
        if (j < 66)       { p = 0;          q = j; }
        else if (j < 132) { p = 65;         q = j - 66; }
        else if (j < 196) { p = j - 132 + 1; q = 0; }
        else              { p = j - 196 + 1; q = 65; }
        hb[(size_t)co * 4356 + p * 66 + q] = 0.f;
    }
}

// ---------------- conv2 weight prep: [co][ci][t] -> fragment order ----------
// g_w2f[t][((ks*16+nf)*32+lane)*2+z] = tf32( w2[co=nf*8+lane/4][ci=ks*8+lane%4+4z][t] )
__global__ __launch_bounds__(256) void w2f_kernel(const float* __restrict__ w2) {
    int i = blockIdx.x * 256 + threadIdx.x;
    if (i < 73728) {
        int t = i / 8192;
        int r = i - t * 8192;
        int z = r & 1;
        int lane = (r >> 1) & 31;
        int idx2 = r >> 6;
        int nf = idx2 & 15, ks = idx2 >> 4;
        int co = nf * 8 + (lane >> 2);
        int ci = ks * 8 + (lane & 3) + 4 * z;
        g_w2f[i] = tf32r(w2[(co * 64 + ci) * 9 + t]);
    }
}

// ---------------- conv1 + relu + maxpool2 -> padded NCHW (tf32-rounded) -----
__global__ __launch_bounds__(256) void conv1_kernel(const float* __restrict__ x,
                                                    const float* __restrict__ w,
                                                    const float* __restrict__ bias) {
    __shared__ float s_in[3*34*34];
    __shared__ float s_w[64*27];
    __shared__ float s_b[64];
    int b  = blockIdx.y;
    int tY = blockIdx.x >> 2, tX = blockIdx.x & 3;
    int Py0 = tY*16, Px0 = tX*16;
    int tid = threadIdx.x;

    for (int i = tid; i < 64*27; i += 256) s_w[i] = w[i];
    if (tid < 64) s_b[tid] = bias[tid];

    const float* xb = x + (size_t)b*3*128*128;
    for (int i = tid; i < 3*34*34; i += 256) {
        int ci = i / 1156, rem2 = i % 1156;
        int ly = rem2 / 34, lx = rem2 % 34;
        int gy = 2*Py0 - 1 + ly, gx = 2*Px0 - 1 + lx;
        float v = 0.f;
        if (gy >= 0 && gy < 128 && gx >= 0 && gx < 128)
            v = xb[(size_t)ci*16384 + gy*128 + gx];
        s_in[i] = v;
    }
    __syncthreads();

    int ty = tid >> 4, tx = tid & 15;
    float win[3][16];
    #pragma unroll
    for (int ci = 0; ci < 3; ci++)
        #pragma unroll
        for (int r = 0; r < 4; r++)
            #pragma unroll
            for (int c = 0; c < 4; c++)
                win[ci][r*4+c] = s_in[ci*1156 + (2*ty + r)*34 + (2*tx + c)];

    int Y = Py0 + ty, X = Px0 + tx;
    float* outp = g_h1p + (size_t)b*64*4356 + (size_t)(Y+1)*66 + (X+1);
    #pragma unroll 1
    for (int co = 0; co < 64; co++) {
        float a0=0.f, a1=0.f, a2=0.f, a3=0.f;
        const float* wp = &s_w[co*27];
        #pragma unroll
        for (int ci = 0; ci < 3; ci++)
            #pragma unroll
            for (int k = 0; k < 9; k++) {
                int ky = k/3, kx = k%3;
                float wv = wp[ci*9+k];
                a0 = fmaf(win[ci][ ky   *4 + kx    ], wv, a0);
                a1 = fmaf(win[ci][ ky   *4 + kx + 1], wv, a1);
                a2 = fmaf(win[ci][(ky+1)*4 + kx    ], wv, a2);
                a3 = fmaf(win[ci][(ky+1)*4 + kx + 1], wv, a3);
            }
        float m = fmaxf(fmaxf(a0,a1), fmaxf(a2,a3));
        outp[(size_t)co*4356] = tf32r(fmaxf(m + s_b[co], 0.f));
    }
}

// ---------------- conv2 via mma.sync tf32 (implicit GEMM, 9 taps) -----------
// CTA = (batch b, pooled row Y). M=128 (2 pre-pool rows x 64 x), N=128 co.
// smem: slab [ci:64][row:4][x:66] (stride 264 words), B double buffer 2x8192
// floats (fragment order). Epilogue reuses slab region for C staging.
__global__ __launch_bounds__(256) void conv2_mma_kernel(const float* __restrict__ b2) {
    extern __shared__ float sm[];
    const int tid = threadIdx.x;
    const int lane = tid & 31, wid = tid >> 5;
    const int warp_m = wid >> 1, warp_n = wid & 1;
    const int bY = blockIdx.x;
    const int b = bY >> 5, Y = bY & 31;

    uint32_t slab_b = smem_u32(sm);

    // issue slab (rows 2Y..2Y+3, all 64 ci) + B tap0, one cp.async group
    {
        const float* sb0 = g_h1p + (size_t)b*278784 + 132*Y;
        for (int i = tid; i < 8448; i += 256) {
            int ci = i / 132, w2i = i - ci*132;
            cpa8(slab_b + (uint32_t)i*8u, sb0 + (size_t)ci*4356 + w2i*2);
        }
        uint32_t bst0 = slab_b + 16896u*4u;
        for (int i = tid; i < 2048; i += 256)          // 2048 x 16B = full 32KB tap
            cpa16(bst0 + (uint32_t)i*16u, g_w2f + i*4);
        asm volatile("cp.async.commit_group;" ::: "memory");
    }

    float c[2][8][4];
    #pragma unroll
    for (int mf = 0; mf < 2; mf++)
        #pragma unroll
        for (int nf = 0; nf < 8; nf++)
            #pragma unroll
            for (int r = 0; r < 4; r++) c[mf][nf][r] = 0.f;

    const int ry  = warp_m >> 1;
    const int xw0 = (warp_m & 1) * 32;

    #pragma unroll 1
    for (int t = 0; t < 9; t++) {
        asm volatile("cp.async.wait_group 0;" ::: "memory");
        __syncthreads();
        if (t < 8) {   // prefetch next tap's weights into the other buffer
            uint32_t bstn = slab_b + (16896u + (uint32_t)((t+1)&1)*8192u)*4u;
            const float* wsrc = g_w2f + (t+1)*8192;
            for (int i = tid; i < 2048; i += 256)      // full 32KB tap
                cpa16(bstn + (uint32_t)i*16u, wsrc + i*4);
            asm volatile("cp.async.commit_group;" ::: "memory");
        }
        const int ky = t / 3, kx = t - ky*3;
        const float* Abase = sm + (ry + ky)*66 + kx + xw0 + (lane >> 2) + (lane & 3)*264;
        const float* Bbase = sm + 16896 + (t & 1)*8192 + warp_n*512 + lane*2;
        #pragma unroll
        for (int ks = 0; ks < 8; ks++) {
            const float* Ak = Abase + ks*2112;   // ks*8 channels * 264
            uint32_t a[2][4];
            #pragma unroll
            for (int mf = 0; mf < 2; mf++) {
                const float* Am = Ak + mf*16;
                a[mf][0] = __float_as_uint(Am[0]);
                a[mf][1] = __float_as_uint(Am[8]);
                a[mf][2] = __float_as_uint(Am[1056]);   // ci+4
                a[mf][3] = __float_as_uint(Am[1064]);
            }
            const float* Bk = Bbase + ks*1024;
            uint32_t bb[8][2];
            #pragma unroll
            for (int nf = 0; nf < 8; nf++) {
                float2 v = *reinterpret_cast<const float2*>(Bk + nf*64);
                bb[nf][0] = __float_as_uint(v.x);
                bb[nf][1] = __float_as_uint(v.y);
            }
            #pragma unroll
            for (int mf = 0; mf < 2; mf++)
                #pragma unroll
                for (int nf = 0; nf < 8; nf++)
                    mma16n8k8(c[mf][nf], a[mf], bb[nf]);
        }
    }

    // ---- epilogue: stage C, 2x2 maxpool + bias + relu, write NHWC g_f ----
    __syncthreads();     // everyone done reading slab
    #pragma unroll
    for (int mf = 0; mf < 2; mf++)
        #pragma unroll
        for (int nf = 0; nf < 8; nf++) {
            int m0 = warp_m*32 + mf*16 + (lane >> 2);
            int n0 = warp_n*64 + nf*8 + (lane & 3)*2;
            *reinterpret_cast<float2*>(sm + m0*132 + n0)     = make_float2(c[mf][nf][0], c[mf][nf][1]);
            *reinterpret_cast<float2*>(sm + (m0+8)*132 + n0) = make_float2(c[mf][nf][2], c[mf][nf][3]);
        }
    __syncthreads();
    float* gf = g_f + (((size_t)b*32 + Y)*32)*128;
    #pragma unroll
    for (int u = 0; u < 16; u++) {
        int idx = tid + u*256;
        int cch = idx & 127, xo = idx >> 7;
        float v0 = fmaxf(sm[(2*xo)*132 + cch],    sm[(2*xo+1)*132 + cch]);
        float v1 = fmaxf(sm[(64+2*xo)*132 + cch], sm[(64+2*xo+1)*132 + cch]);
        float v = fmaxf(fmaxf(v0, v1) + __ldg(&b2[cch]), 0.f);
        gf[(size_t)xo*128 + cch] = v;
    }
}

// ---------------- fused QKV projection -------------------------------------
__global__ __launch_bounds__(256) void qkv_kernel(
    const float* __restrict__ qw, const float* __restrict__ qb,
    const float* __restrict__ kw, const float* __restrict__ kb,
    const float* __restrict__ vw, const float* __restrict__ vb) {
    extern __shared__ float smem[];
    float* s_f = smem;          // 32*128 = 4096
    float* s_w = smem + 4096;   // 128*193 = 24704
    int tid = threadIdx.x;
    int t0  = blockIdx.x * 32;

    for (int i = tid; i < 4096; i += 256) s_f[i] = g_f[(size_t)t0*128 + i];
    for (int i = tid; i < 24576; i += 256) {
        int o = i >> 7, kk = i & 127;
        float v;
        if (o < 64)       v = qw[i];
        else if (o < 128) v = kw[i - 8192];
        else              v = vw[i - 16384];
        s_w[kk*193 + o] = v;
    }
    __syncthreads();

    int og = tid & 31, tg = tid >> 5;
    float acc[4][6];
    #pragma unroll
    for (int a = 0; a < 4; a++)
        #pragma unroll
        for (int j = 0; j < 6; j++) acc[a][j] = 0.f;

    #pragma unroll 2
    for (int kk = 0; kk < 128; kk++) {
        float fv[4];
        #pragma unroll
        for (int a = 0; a < 4; a++) fv[a] = s_f[(tg*4+a)*128 + kk];
        const float* wrow = s_w + kk*193 + og*6;
        #pragma unroll
        for (int j = 0; j < 6; j++) {
            float wv = wrow[j];
            #pragma unroll
            for (int a = 0; a < 4; a++) acc[a][j] = fmaf(fv[a], wv, acc[a][j]);
        }
    }

    #pragma unroll
    for (int a = 0; a < 4; a++) {
        int t = t0 + tg*4 + a;
        int bidx = t >> 10, rem = t & 1023;
        #pragma unroll
        for (int j = 0; j < 6; j++) {
            int o = og*6 + j;
            float val = acc[a][j];
            if (o < 64) {
                val = (val + __ldg(&qb[o])) * 0.25f;   // DH^-0.5
                int head = o >> 4, d = o & 15;
                g_q[((size_t)(bidx*4 + head)*1024 + rem)*16 + d] = val;
            } else if (o < 128) {
                int cc = o - 64; val += __ldg(&kb[cc]);
                int head = cc >> 4, d = cc & 15;
                g_k[((size_t)(bidx*4 + head)*1024 + rem)*16 + d] = val;
            } else {
                int cc = o - 128; val += __ldg(&vb[cc]);
                int head = cc >> 4, d = cc & 15;
                g_v[((size_t)(bidx*4 + head)*1024 + rem)*16 + d] = val;
            }
        }
    }
}

// ---------------- axial row attention (along W) -----------------------------
__global__ __launch_bounds__(256) void attn_row_kernel(const float* __restrict__ rel_w) {
    int line = blockIdx.x;
    int y = line & 31, bh = line >> 5;
    int head = bh & 3, b = bh >> 2;
    __shared__ float qs[512], ks[512], vs[512], ps[1024];
    int tid = threadIdx.x;
    size_t base = ((size_t)bh*32 + y)*512;
    for (int i = tid; i < 512; i += 256) {
        qs[i] = g_q[base + i];
        ks[i] = g_k[base + i];
        vs[i] = g_v[base + i];
    }
    __syncthreads();
    for (int e = tid; e < 1024; e += 256) {
        int i = e >> 5, j = e & 31;
        float s = 0.f;
        #pragma unroll
        for (int d = 0; d < 16; d++) s = fmaf(qs[i*16+d], ks[j*16+d], s);
        ps[e] = s + __ldg(&rel_w[head*63 + i - j + 31]);
    }
    __syncthreads();
    int lane = tid & 31, w = tid >> 5;
    #pragma unroll
    for (int r = 0; r < 4; r++) {
        int i = w*4 + r;
        float xv = ps[i*32 + lane];
        float m = xv;
        #pragma unroll
        for (int off = 16; off; off >>= 1) m = fmaxf(m, __shfl_xor_sync(0xffffffffu, m, off));
        float e2 = __expf(xv - m);
        float ss = e2;
        #pragma unroll
        for (int off = 16; off; off >>= 1) ss += __shfl_xor_sync(0xffffffffu, ss, off);
        ps[i*32 + lane] = e2 / ss;
    }
    __syncthreads();
    for (int e = tid; e < 512; e += 256) {
        int i = e >> 4, d = e & 15;
        float o = 0.f;
        #pragma unroll
        for (int j = 0; j < 32; j++) o = fmaf(ps[i*32+j], vs[j*16+d], o);
        int token = (b*32 + y)*32 + i;
        g_o[(size_t)token*64 + head*16 + d] = o;
    }
}

// ---------------- axial column attention (along H), accumulates into g_o ----
__global__ __launch_bounds__(256) void attn_col_kernel(const float* __restrict__ rel_h) {
    int line = blockIdx.x;
    int xcol = line & 31, bh = line >> 5;
    int head = bh & 3, b = bh >> 2;
    __shared__ float qs[512], ks[512], vs[512], ps[1024];
    int tid = threadIdx.x;
    for (int idx = tid; idx < 512; idx += 256) {
        int i = idx >> 4, d = idx & 15;
        size_t gidx = (((size_t)bh*32 + i)*32 + xcol)*16 + d;
        qs[idx] = g_q[gidx]; ks[idx] = g_k[gidx]; vs[idx] = g_v[gidx];
    }
    __syncthreads();
    for (int e = tid; e < 1024; e += 256) {
        int i = e >> 5, j = e & 31;
        float s = 0.f;
        #pragma unroll
        for (int d = 0; d < 16; d++) s = fmaf(qs[i*16+d], ks[j*16+d], s);
        ps[e] = s + __ldg(&rel_h[head*63 + i - j + 31]);
    }
    __syncthreads();
    int lane = tid & 31, w = tid >> 5;
    #pragma unroll
    for (int r = 0; r < 4; r++) {
        int i = w*4 + r;
        float xv = ps[i*32 + lane];
        float m = xv;
        #pragma unroll
        for (int off = 16; off; off >>= 1) m = fmaxf(m, __shfl_xor_sync(0xffffffffu, m, off));
        float e2 = __expf(xv - m);
        float ss = e2;
        #pragma unroll
        for (int off = 16; off; off >>= 1) ss += __shfl_xor_sync(0xffffffffu, ss, off);
        ps[i*32 + lane] = e2 / ss;
    }
    __syncthreads();
    for (int e = tid; e < 512; e += 256) {
        int i = e >> 4, d = e & 15;
        float o = 0.f;
        #pragma unroll
        for (int j = 0; j < 32; j++) o = fmaf(ps[i*32+j], vs[j*16+d], o);
        int token = (b*32 + i)*32 + xcol;
        float* op = &g_o[(size_t)token*64 + head*16 + d];
        *op += o;
    }
}

// ---------------- final: mean-pool + (linear-folded) proj + fc --------------
__global__ __launch_bounds__(256) void reduce_kernel(
    const float* __restrict__ proj_w, const float* __restrict__ proj_b,
    const float* __restrict__ fc_w,   const float* __restrict__ fc_b,
    float* __restrict__ out) {
    int b = blockIdx.x, tid = threadIdx.x;
    __shared__ float s_tmp[256], s_tmpo[256], s_meanf[128], s_meano[64], s_pooled[128];
    const float* fb = g_f + (size_t)b*1024*128;
    int c = tid & 127, half = tid >> 7;
    float acc = 0.f;
    for (int t = half; t < 1024; t += 2) acc += fb[t*128 + c];
    s_tmp[tid] = acc;
    const float* ob = g_o + (size_t)b*1024*64;
    int c2 = tid & 63, grp = tid >> 6;
    float acco = 0.f;
    for (int t = grp; t < 1024; t += 4) acco += ob[t*64 + c2];
    s_tmpo[tid] = acco;
    __syncthreads();
    if (tid < 128) s_meanf[tid] = (s_tmp[tid] + s_tmp[tid+128]) * (1.f/1024.f);
    if (tid < 64)  s_meano[tid] = (s_tmpo[tid] + s_tmpo[tid+64] + s_tmpo[tid+128] + s_tmpo[tid+192]) * (1.f/1024.f);
    __syncthreads();
    if (tid < 128) {
        float v2 = s_meanf[tid] + proj_b[tid];
        #pragma unroll 8
        for (int k2 = 0; k2 < 64; k2++) v2 = fmaf(proj_w[tid*64+k2], s_meano[k2], v2);
        s_pooled[tid] = v2;
    }
    __syncthreads();
    if (tid < 10) {
        float v2 = fc_b[tid];
        #pragma unroll 8
        for (int cc = 0; cc < 128; cc++) v2 = fmaf(fc_w[tid*128+cc], s_pooled[cc], v2);
        out[b*10 + tid] = v2;
    }
}

// ---------------- launch ----------------------------------------------------
extern "C" void kernel_launch(void* const* d_in, const int* in_sizes, int n_in,
                              void* d_out, int out_size) {
    (void)in_sizes; (void)n_in; (void)out_size;
    const float* x       = (const float*)d_in[0];
    const float* conv1_w = (const float*)d_in[1];
    const float* conv1_b = (const float*)d_in[2];
    const float* conv2_w = (const float*)d_in[3];
    const float* conv2_b = (const float*)d_in[4];
    const float* q_w     = (const float*)d_in[5];
    const float* q_b     = (const float*)d_in[6];
    const float* k_w     = (const float*)d_in[7];
    const float* k_b     = (const float*)d_in[8];
    const float* v_w     = (const float*)d_in[9];
    const float* v_b     = (const float*)d_in[10];
    const float* proj_w  = (const float*)d_in[11];
    const float* proj_b  = (const float*)d_in[12];
    const float* rel_h   = (const float*)d_in[13];
    const float* rel_w   = (const float*)d_in[14];
    const float* fc_w    = (const float*)d_in[15];
    const float* fc_b    = (const float*)d_in[16];
    float* out = (float*)d_out;

    const int CONV2_SMEM = 33280 * 4;   // slab 16896 + 2x8192 B floats = 133120 B
    cudaFuncSetAttribute(conv2_mma_kernel, cudaFuncAttributeMaxDynamicSharedMemorySize, CONV2_SMEM);
    cudaFuncSetAttribute(qkv_kernel, cudaFuncAttributeMaxDynamicSharedMemorySize, (4096+24704)*4);

    zero_border_kernel<<<32, 256>>>();
    w2f_kernel<<<288, 256>>>(conv2_w);
    conv1_kernel<<<dim3(16,32), 256>>>(x, conv1_w, conv1_b);
    conv2_mma_kernel<<<1024, 256, CONV2_SMEM>>>(conv2_b);
    qkv_kernel<<<1024, 256, (4096+24704)*4>>>(q_w, q_b, k_w, k_b, v_w, v_b);
    attn_row_kernel<<<4096, 256>>>(rel_w);
    attn_col_kernel<<<4096, 256>>>(rel_h);
    reduce_kernel<<<32, 256>>>(proj_w, proj_b, fc_w, fc_b, out);
}

// round 5
// speedup vs baseline: 2.0943x; 1.1643x over previous
#include <cuda_runtime.h>
#include <cstdint>

// ---------------- scratch (static device globals; no allocations) ----------
__device__ float g_h1p[32u*64*66*66];    // conv1 out, padded NCHW [32][64][66][66]
__device__ float g_w2f[9*8192];          // conv2 weights, mma-fragment order (tf32-rounded)
__device__ float g_f [32u*32*32*128];    // conv2 out, NHWC [32,32,32,128]
__device__ float g_q [32u*4*1024*16];    // [b,head,y,x,d]
__device__ float g_k [32u*4*1024*16];
__device__ float g_v [32u*4*1024*16];
__device__ float g_o [32u*1024*64];      // [b,y,x, head*16+d]

// ---------------- helpers ----------------------------------------------------
__device__ __forceinline__ uint32_t smem_u32(const void* p) {
    uint32_t a;
    asm("{ .reg .u64 t; cvta.to.shared.u64 t, %1; cvt.u32.u64 %0, t; }"
        : "=r"(a) : "l"(p));
    return a;
}
__device__ __forceinline__ float tf32r(float x) {
    uint32_t u;
    asm("cvt.rna.tf32.f32 %0, %1;" : "=r"(u) : "f"(x));
    return __uint_as_float(u);
}
__device__ __forceinline__ void cpa16(uint32_t d, const void* s) {
    asm volatile("cp.async.cg.shared.global [%0], [%1], 16;" :: "r"(d), "l"(s));
}
__device__ __forceinline__ void cpa8(uint32_t d, const void* s) {
    asm volatile("cp.async.ca.shared.global [%0], [%1], 8;" :: "r"(d), "l"(s));
}
__device__ __forceinline__ void mma16n8k8(float* c, const uint32_t* a, const uint32_t* b) {
    asm volatile("mma.sync.aligned.m16n8k8.row.col.f32.tf32.tf32.f32 "
        "{%0,%1,%2,%3}, {%4,%5,%6,%7}, {%8,%9}, {%0,%1,%2,%3};"
        : "+f"(c[0]), "+f"(c[1]), "+f"(c[2]), "+f"(c[3])
        : "r"(a[0]), "r"(a[1]), "r"(a[2]), "r"(a[3]), "r"(b[0]), "r"(b[1]));
}
__device__ __forceinline__ float dot16(float4 q0, float4 q1, float4 q2, float4 q3,
                                       const float4* kp) {
    float4 k0 = kp[0], k1 = kp[1], k2 = kp[2], k3 = kp[3];
    float s = q0.x*k0.x;
    s = fmaf(q0.y, k0.y, s); s = fmaf(q0.z, k0.z, s); s = fmaf(q0.w, k0.w, s);
    s = fmaf(q1.x, k1.x, s); s = fmaf(q1.y, k1.y, s); s = fmaf(q1.z, k1.z, s); s = fmaf(q1.w, k1.w, s);
    s = fmaf(q2.x, k2.x, s); s = fmaf(q2.y, k2.y, s); s = fmaf(q2.z, k2.z, s); s = fmaf(q2.w, k2.w, s);
    s = fmaf(q3.x, k3.x, s); s = fmaf(q3.y, k3.y, s); s = fmaf(q3.z, k3.z, s); s = fmaf(q3.w, k3.w, s);
    return s;
}

// ---------------- border zero for padded NCHW h1 ----------------------------
__global__ __launch_bounds__(256) void zero_border_kernel() {
    int b = blockIdx.x;
    float* hb = g_h1p + (size_t)b * 64 * 4356;
    for (int i = threadIdx.x; i < 16640; i += 256) {
        int co = i / 260, j = i % 260;
        int p, q;
        if (j < 66)       { p = 0;          q = j; }
        else if (j < 132) { p = 65;         q = j - 66; }
        else if (j < 196) { p = j - 132 + 1; q = 0; }
        else              { p = j - 196 + 1; q = 65; }
        hb[(size_t)co * 4356 + p * 66 + q] = 0.f;
    }
}

// ---------------- conv2 weight prep: [co][ci][t] -> fragment order ----------
__global__ __launch_bounds__(256) void w2f_kernel(const float* __restrict__ w2) {
    int i = blockIdx.x * 256 + threadIdx.x;
    if (i < 73728) {
        int t = i / 8192;
        int r = i - t * 8192;
        int z = r & 1;
        int lane = (r >> 1) & 31;
        int idx2 = r >> 6;
        int nf = idx2 & 15, ks = idx2 >> 4;
        int co = nf * 8 + (lane >> 2);
        int ci = ks * 8 + (lane & 3) + 4 * z;
        g_w2f[i] = tf32r(w2[(co * 64 + ci) * 9 + t]);
    }
}

// ---------------- conv1 + relu + maxpool2 -> padded NCHW (tf32-rounded) -----
__global__ __launch_bounds__(256) void conv1_kernel(const float* __restrict__ x,
                                                    const float* __restrict__ w,
                                                    const float* __restrict__ bias) {
    __shared__ float s_in[3*34*34];
    __shared__ float s_w[64*27];
    __shared__ float s_b[64];
    int b  = blockIdx.y;
    int tY = blockIdx.x >> 2, tX = blockIdx.x & 3;
    int Py0 = tY*16, Px0 = tX*16;
    int tid = threadIdx.x;

    for (int i = tid; i < 64*27; i += 256) s_w[i] = w[i];
    if (tid < 64) s_b[tid] = bias[tid];

    const float* xb = x + (size_t)b*3*128*128;
    for (int i = tid; i < 3*34*34; i += 256) {
        int ci = i / 1156, rem2 = i % 1156;
        int ly = rem2 / 34, lx = rem2 % 34;
        int gy = 2*Py0 - 1 + ly, gx = 2*Px0 - 1 + lx;
        float v = 0.f;
        if (gy >= 0 && gy < 128 && gx >= 0 && gx < 128)
            v = xb[(size_t)ci*16384 + gy*128 + gx];
        s_in[i] = v;
    }
    __syncthreads();

    int ty = tid >> 4, tx = tid & 15;
    float win[3][16];
    #pragma unroll
    for (int ci = 0; ci < 3; ci++)
        #pragma unroll
        for (int r = 0; r < 4; r++)
            #pragma unroll
            for (int c = 0; c < 4; c++)
                win[ci][r*4+c] = s_in[ci*1156 + (2*ty + r)*34 + (2*tx + c)];

    int Y = Py0 + ty, X = Px0 + tx;
    float* outp = g_h1p + (size_t)b*64*4356 + (size_t)(Y+1)*66 + (X+1);
    #pragma unroll 1
    for (int co = 0; co < 64; co++) {
        float a0=0.f, a1=0.f, a2=0.f, a3=0.f;
        const float* wp = &s_w[co*27];
        #pragma unroll
        for (int ci = 0; ci < 3; ci++)
            #pragma unroll
            for (int k = 0; k < 9; k++) {
                int ky = k/3, kx = k%3;
                float wv = wp[ci*9+k];
                a0 = fmaf(win[ci][ ky   *4 + kx    ], wv, a0);
                a1 = fmaf(win[ci][ ky   *4 + kx + 1], wv, a1);
                a2 = fmaf(win[ci][(ky+1)*4 + kx    ], wv, a2);
                a3 = fmaf(win[ci][(ky+1)*4 + kx + 1], wv, a3);
            }
        float m = fmaxf(fmaxf(a0,a1), fmaxf(a2,a3));
        outp[(size_t)co*4356] = tf32r(fmaxf(m + s_b[co], 0.f));
    }
}

// ---------------- conv2 via mma.sync tf32 (implicit GEMM, 9 taps) -----------
__global__ __launch_bounds__(256) void conv2_mma_kernel(const float* __restrict__ b2) {
    extern __shared__ float sm[];
    const int tid = threadIdx.x;
    const int lane = tid & 31, wid = tid >> 5;
    const int warp_m = wid >> 1, warp_n = wid & 1;
    const int bY = blockIdx.x;
    const int b = bY >> 5, Y = bY & 31;

    uint32_t slab_b = smem_u32(sm);

    {
        const float* sb0 = g_h1p + (size_t)b*278784 + 132*Y;
        for (int i = tid; i < 8448; i += 256) {
            int ci = i / 132, w2i = i - ci*132;
            cpa8(slab_b + (uint32_t)i*8u, sb0 + (size_t)ci*4356 + w2i*2);
        }
        uint32_t bst0 = slab_b + 16896u*4u;
        for (int i = tid; i < 2048; i += 256)
            cpa16(bst0 + (uint32_t)i*16u, g_w2f + i*4);
        asm volatile("cp.async.commit_group;" ::: "memory");
    }

    float c[2][8][4];
    #pragma unroll
    for (int mf = 0; mf < 2; mf++)
        #pragma unroll
        for (int nf = 0; nf < 8; nf++)
            #pragma unroll
            for (int r = 0; r < 4; r++) c[mf][nf][r] = 0.f;

    const int ry  = warp_m >> 1;
    const int xw0 = (warp_m & 1) * 32;

    #pragma unroll 1
    for (int t = 0; t < 9; t++) {
        asm volatile("cp.async.wait_group 0;" ::: "memory");
        __syncthreads();
        if (t < 8) {
            uint32_t bstn = slab_b + (16896u + (uint32_t)((t+1)&1)*8192u)*4u;
            const float* wsrc = g_w2f + (t+1)*8192;
            for (int i = tid; i < 2048; i += 256)
                cpa16(bstn + (uint32_t)i*16u, wsrc + i*4);
            asm volatile("cp.async.commit_group;" ::: "memory");
        }
        const int ky = t / 3, kx = t - ky*3;
        const float* Abase = sm + (ry + ky)*66 + kx + xw0 + (lane >> 2) + (lane & 3)*264;
        const float* Bbase = sm + 16896 + (t & 1)*8192 + warp_n*512 + lane*2;
        #pragma unroll
        for (int ks = 0; ks < 8; ks++) {
            const float* Ak = Abase + ks*2112;
            uint32_t a[2][4];
            #pragma unroll
            for (int mf = 0; mf < 2; mf++) {
                const float* Am = Ak + mf*16;
                a[mf][0] = __float_as_uint(Am[0]);
                a[mf][1] = __float_as_uint(Am[8]);
                a[mf][2] = __float_as_uint(Am[1056]);
                a[mf][3] = __float_as_uint(Am[1064]);
            }
            const float* Bk = Bbase + ks*1024;
            uint32_t bb[8][2];
            #pragma unroll
            for (int nf = 0; nf < 8; nf++) {
                float2 v = *reinterpret_cast<const float2*>(Bk + nf*64);
                bb[nf][0] = __float_as_uint(v.x);
                bb[nf][1] = __float_as_uint(v.y);
            }
            #pragma unroll
            for (int mf = 0; mf < 2; mf++)
                #pragma unroll
                for (int nf = 0; nf < 8; nf++)
                    mma16n8k8(c[mf][nf], a[mf], bb[nf]);
        }
    }

    __syncthreads();
    #pragma unroll
    for (int mf = 0; mf < 2; mf++)
        #pragma unroll
        for (int nf = 0; nf < 8; nf++) {
            int m0 = warp_m*32 + mf*16 + (lane >> 2);
            int n0 = warp_n*64 + nf*8 + (lane & 3)*2;
            *reinterpret_cast<float2*>(sm + m0*132 + n0)     = make_float2(c[mf][nf][0], c[mf][nf][1]);
            *reinterpret_cast<float2*>(sm + (m0+8)*132 + n0) = make_float2(c[mf][nf][2], c[mf][nf][3]);
        }
    __syncthreads();
    float* gf = g_f + (((size_t)b*32 + Y)*32)*128;
    #pragma unroll
    for (int u = 0; u < 16; u++) {
        int idx = tid + u*256;
        int cch = idx & 127, xo = idx >> 7;
        float v0 = fmaxf(sm[(2*xo)*132 + cch],    sm[(2*xo+1)*132 + cch]);
        float v1 = fmaxf(sm[(64+2*xo)*132 + cch], sm[(64+2*xo+1)*132 + cch]);
        float v = fmaxf(fmaxf(v0, v1) + __ldg(&b2[cch]), 0.f);
        gf[(size_t)xo*128 + cch] = v;
    }
}

// ---------------- fused QKV projection -------------------------------------
__global__ __launch_bounds__(256) void qkv_kernel(
    const float* __restrict__ qw, const float* __restrict__ qb,
    const float* __restrict__ kw, const float* __restrict__ kb,
    const float* __restrict__ vw, const float* __restrict__ vb) {
    extern __shared__ float smem[];
    float* s_f = smem;          // 32*128 = 4096
    float* s_w = smem + 4096;   // 128*193 = 24704
    int tid = threadIdx.x;
    int t0  = blockIdx.x * 32;

    for (int i = tid; i < 4096; i += 256) s_f[i] = g_f[(size_t)t0*128 + i];
    for (int i = tid; i < 24576; i += 256) {
        int o = i >> 7, kk = i & 127;
        float v;
        if (o < 64)       v = qw[i];
        else if (o < 128) v = kw[i - 8192];
        else              v = vw[i - 16384];
        s_w[kk*193 + o] = v;
    }
    __syncthreads();

    int og = tid & 31, tg = tid >> 5;
    float acc[4][6];
    #pragma unroll
    for (int a = 0; a < 4; a++)
        #pragma unroll
        for (int j = 0; j < 6; j++) acc[a][j] = 0.f;

    #pragma unroll 2
    for (int kk = 0; kk < 128; kk++) {
        float fv[4];
        #pragma unroll
        for (int a = 0; a < 4; a++) fv[a] = s_f[(tg*4+a)*128 + kk];
        const float* wrow = s_w + kk*193 + og*6;
        #pragma unroll
        for (int j = 0; j < 6; j++) {
            float wv = wrow[j];
            #pragma unroll
            for (int a = 0; a < 4; a++) acc[a][j] = fmaf(fv[a], wv, acc[a][j]);
        }
    }

    #pragma unroll
    for (int a = 0; a < 4; a++) {
        int t = t0 + tg*4 + a;
        int bidx = t >> 10, rem = t & 1023;
        #pragma unroll
        for (int j = 0; j < 6; j++) {
            int o = og*6 + j;
            float val = acc[a][j];
            if (o < 64) {
                val = (val + __ldg(&qb[o])) * 0.25f;   // DH^-0.5
                int head = o >> 4, d = o & 15;
                g_q[((size_t)(bidx*4 + head)*1024 + rem)*16 + d] = val;
            } else if (o < 128) {
                int cc = o - 64; val += __ldg(&kb[cc]);
                int head = cc >> 4, d = cc & 15;
                g_k[((size_t)(bidx*4 + head)*1024 + rem)*16 + d] = val;
            } else {
                int cc = o - 128; val += __ldg(&vb[cc]);
                int head = cc >> 4, d = cc & 15;
                g_v[((size_t)(bidx*4 + head)*1024 + rem)*16 + d] = val;
            }
        }
    }
}

// ---------------- fused axial attention (row + col), one CTA per (b,head) ---
// smem: ks/vs full 1024x16 planes (128KB) + bias tables. 256 threads.
// Phase 1 (rows):  warp lanes share row y -> k/v reads are warp-broadcast.
// Phase 2 (cols):  warp lanes share col x -> k/v reads are warp-broadcast.
// o accumulated via g_o (phase1 '=', phase2 '+='), intra-CTA visibility via
// __syncthreads (block-level global ordering).
__global__ __launch_bounds__(256) void attn_fused_kernel(const float* __restrict__ rel_w,
                                                         const float* __restrict__ rel_h) {
    extern __shared__ float asmem[];
    float* ks  = asmem;            // 16384
    float* vs  = asmem + 16384;    // 16384
    float* srw = asmem + 32768;    // 64
    float* srh = asmem + 32832;    // 64
    const int bh = blockIdx.x;
    const int head = bh & 3, b = bh >> 2;
    const int tid = threadIdx.x;
    const int l = tid & 31, w = tid >> 5;

    {
        const float4* gk = (const float4*)(g_k + (size_t)bh*16384);
        const float4* gv = (const float4*)(g_v + (size_t)bh*16384);
        float4* k4 = (float4*)ks;
        float4* v4 = (float4*)vs;
        for (int i = tid; i < 4096; i += 256) { k4[i] = gk[i]; v4[i] = gv[i]; }
        if (tid < 63) { srw[tid] = rel_w[head*63 + tid]; srh[tid] = rel_h[head*63 + tid]; }
    }
    __syncthreads();

    const float* gq = g_q + (size_t)bh*16384;
    float* go = g_o + (size_t)b*65536 + head*16;

    // ---- phase 1: row attention; token t = y*32 + l, y = w + 8u ----
    #pragma unroll 1
    for (int u = 0; u < 4; u++) {
        const int y = w + 8*u;
        const int t = y*32 + l;
        const float4* qp = (const float4*)(gq + t*16);
        const float4 q0 = qp[0], q1 = qp[1], q2 = qp[2], q3 = qp[3];
        float sc[32];
        float mx = -1e30f;
        #pragma unroll
        for (int j = 0; j < 32; j++) {
            float s = dot16(q0, q1, q2, q3, (const float4*)(ks + (y*32 + j)*16));
            s += srw[l - j + 31];
            sc[j] = s;
            mx = fmaxf(mx, s);
        }
        float ssum = 0.f;
        #pragma unroll
        for (int j = 0; j < 32; j++) { sc[j] = __expf(sc[j] - mx); ssum += sc[j]; }
        const float inv = 1.f / ssum;
        float4 o0 = {0,0,0,0}, o1 = {0,0,0,0}, o2 = {0,0,0,0}, o3 = {0,0,0,0};
        #pragma unroll
        for (int j = 0; j < 32; j++) {
            const float4* vp = (const float4*)(vs + (y*32 + j)*16);
            const float p = sc[j];
            float4 v0 = vp[0], v1 = vp[1], v2 = vp[2], v3 = vp[3];
            o0.x = fmaf(p, v0.x, o0.x); o0.y = fmaf(p, v0.y, o0.y);
            o0.z = fmaf(p, v0.z, o0.z); o0.w = fmaf(p, v0.w, o0.w);
            o1.x = fmaf(p, v1.x, o1.x); o1.y = fmaf(p, v1.y, o1.y);
            o1.z = fmaf(p, v1.z, o1.z); o1.w = fmaf(p, v1.w, o1.w);
            o2.x = fmaf(p, v2.x, o2.x); o2.y = fmaf(p, v2.y, o2.y);
            o2.z = fmaf(p, v2.z, o2.z); o2.w = fmaf(p, v2.w, o2.w);
            o3.x = fmaf(p, v3.x, o3.x); o3.y = fmaf(p, v3.y, o3.y);
            o3.z = fmaf(p, v3.z, o3.z); o3.w = fmaf(p, v3.w, o3.w);
        }
        float4* op = (float4*)(go + (size_t)t*64);
        o0.x *= inv; o0.y *= inv; o0.z *= inv; o0.w *= inv;
        o1.x *= inv; o1.y *= inv; o1.z *= inv; o1.w *= inv;
        o2.x *= inv; o2.y *= inv; o2.z *= inv; o2.w *= inv;
        o3.x *= inv; o3.y *= inv; o3.z *= inv; o3.w *= inv;
        op[0] = o0; op[1] = o1; op[2] = o2; op[3] = o3;
    }

    __syncthreads();   // phase-1 g_o writes visible block-wide

    // ---- phase 2: col attention; token t = l*32 + x, x = w + 8u ----
    #pragma unroll 1
    for (int u = 0; u < 4; u++) {
        const int x = w + 8*u;
        const int t = l*32 + x;
        const float4* qp = (const float4*)(gq + t*16);
        const float4 q0 = qp[0], q1 = qp[1], q2 = qp[2], q3 = qp[3];
        float sc[32];
        float mx = -1e30f;
        #pragma unroll
        for (int i = 0; i < 32; i++) {
            float s = dot16(q0, q1, q2, q3, (const float4*)(ks + (i*32 + x)*16));
            s += srh[l - i + 31];
            sc[i] = s;
            mx = fmaxf(mx, s);
        }
        float ssum = 0.f;
        #pragma unroll
        for (int i = 0; i < 32; i++) { sc[i] = __expf(sc[i] - mx); ssum += sc[i]; }
        const float inv = 1.f / ssum;
        float4 o0 = {0,0,0,0}, o1 = {0,0,0,0}, o2 = {0,0,0,0}, o3 = {0,0,0,0};
        #pragma unroll
        for (int i = 0; i < 32; i++) {
            const float4* vp = (const float4*)(vs + (i*32 + x)*16);
            const float p = sc[i];
            float4 v0 = vp[0], v1 = vp[1], v2 = vp[2], v3 = vp[3];
            o0.x = fmaf(p, v0.x, o0.x); o0.y = fmaf(p, v0.y, o0.y);
            o0.z = fmaf(p, v0.z, o0.z); o0.w = fmaf(p, v0.w, o0.w);
            o1.x = fmaf(p, v1.x, o1.x); o1.y = fmaf(p, v1.y, o1.y);
            o1.z = fmaf(p, v1.z, o1.z); o1.w = fmaf(p, v1.w, o1.w);
            o2.x = fmaf(p, v2.x, o2.x); o2.y = fmaf(p, v2.y, o2.y);
            o2.z = fmaf(p, v2.z, o2.z); o2.w = fmaf(p, v2.w, o2.w);
            o3.x = fmaf(p, v3.x, o3.x); o3.y = fmaf(p, v3.y, o3.y);
            o3.z = fmaf(p, v3.z, o3.z); o3.w = fmaf(p, v3.w, o3.w);
        }
        float4* op = (float4*)(go + (size_t)t*64);
        float4 r0 = op[0], r1 = op[1], r2 = op[2], r3 = op[3];
        r0.x = fmaf(o0.x, inv, r0.x); r0.y = fmaf(o0.y, inv, r0.y);
        r0.z = fmaf(o0.z, inv, r0.z); r0.w = fmaf(o0.w, inv, r0.w);
        r1.x = fmaf(o1.x, inv, r1.x); r1.y = fmaf(o1.y, inv, r1.y);
        r1.z = fmaf(o1.z, inv, r1.z); r1.w = fmaf(o1.w, inv, r1.w);
        r2.x = fmaf(o2.x, inv, r2.x); r2.y = fmaf(o2.y, inv, r2.y);
        r2.z = fmaf(o2.z, inv, r2.z); r2.w = fmaf(o2.w, inv, r2.w);
        r3.x = fmaf(o3.x, inv, r3.x); r3.y = fmaf(o3.y, inv, r3.y);
        r3.z = fmaf(o3.z, inv, r3.z); r3.w = fmaf(o3.w, inv, r3.w);
        op[0] = r0; op[1] = r1; op[2] = r2; op[3] = r3;
    }
}

// ---------------- final: mean-pool + (linear-folded) proj + fc --------------
__global__ __launch_bounds__(256) void reduce_kernel(
    const float* __restrict__ proj_w, const float* __restrict__ proj_b,
    const float* __restrict__ fc_w,   const float* __restrict__ fc_b,
    float* __restrict__ out) {
    int b = blockIdx.x, tid = threadIdx.x;
    __shared__ float s_tmp[256], s_tmpo[256], s_meanf[128], s_meano[64], s_pooled[128];
    const float* fb = g_f + (size_t)b*1024*128;
    int c = tid & 127, half = tid >> 7;
    float acc = 0.f;
    for (int t = half; t < 1024; t += 2) acc += fb[t*128 + c];
    s_tmp[tid] = acc;
    const float* ob = g_o + (size_t)b*1024*64;
    int c2 = tid & 63, grp = tid >> 6;
    float acco = 0.f;
    for (int t = grp; t < 1024; t += 4) acco += ob[t*64 + c2];
    s_tmpo[tid] = acco;
    __syncthreads();
    if (tid < 128) s_meanf[tid] = (s_tmp[tid] + s_tmp[tid+128]) * (1.f/1024.f);
    if (tid < 64)  s_meano[tid] = (s_tmpo[tid] + s_tmpo[tid+64] + s_tmpo[tid+128] + s_tmpo[tid+192]) * (1.f/1024.f);
    __syncthreads();
    if (tid < 128) {
        float v2 = s_meanf[tid] + proj_b[tid];
        #pragma unroll 8
        for (int k2 = 0; k2 < 64; k2++) v2 = fmaf(proj_w[tid*64+k2], s_meano[k2], v2);
        s_pooled[tid] = v2;
    }
    __syncthreads();
    if (tid < 10) {
        float v2 = fc_b[tid];
        #pragma unroll 8
        for (int cc = 0; cc < 128; cc++) v2 = fmaf(fc_w[tid*128+cc], s_pooled[cc], v2);
        out[b*10 + tid] = v2;
    }
}

// ---------------- launch ----------------------------------------------------
extern "C" void kernel_launch(void* const* d_in, const int* in_sizes, int n_in,
                              void* d_out, int out_size) {
    (void)in_sizes; (void)n_in; (void)out_size;
    const float* x       = (const float*)d_in[0];
    const float* conv1_w = (const float*)d_in[1];
    const float* conv1_b = (const float*)d_in[2];
    const float* conv2_w = (const float*)d_in[3];
    const float* conv2_b = (const float*)d_in[4];
    const float* q_w     = (const float*)d_in[5];
    const float* q_b     = (const float*)d_in[6];
    const float* k_w     = (const float*)d_in[7];
    const float* k_b     = (const float*)d_in[8];
    const float* v_w     = (const float*)d_in[9];
    const float* v_b     = (const float*)d_in[10];
    const float* proj_w  = (const float*)d_in[11];
    const float* proj_b  = (const float*)d_in[12];
    const float* rel_h   = (const float*)d_in[13];
    const float* rel_w   = (const float*)d_in[14];
    const float* fc_w    = (const float*)d_in[15];
    const float* fc_b    = (const float*)d_in[16];
    float* out = (float*)d_out;

    const int CONV2_SMEM = 33280 * 4;          // 133120 B
    const int ATTN_SMEM  = (32768 + 128) * 4;  // 131584 B
    cudaFuncSetAttribute(conv2_mma_kernel, cudaFuncAttributeMaxDynamicSharedMemorySize, CONV2_SMEM);
    cudaFuncSetAttribute(attn_fused_kernel, cudaFuncAttributeMaxDynamicSharedMemorySize, ATTN_SMEM);
    cudaFuncSetAttribute(qkv_kernel, cudaFuncAttributeMaxDynamicSharedMemorySize, (4096+24704)*4);

    zero_border_kernel<<<32, 256>>>();
    w2f_kernel<<<288, 256>>>(conv2_w);
    conv1_kernel<<<dim3(16,32), 256>>>(x, conv1_w, conv1_b);
    conv2_mma_kernel<<<1024, 256, CONV2_SMEM>>>(conv2_b);
    qkv_kernel<<<1024, 256, (4096+24704)*4>>>(q_w, q_b, k_w, k_b, v_w, v_b);
    attn_fused_kernel<<<128, 256, ATTN_SMEM>>>(rel_w, rel_h);
    reduce_kernel<<<32, 256>>>(proj_w, proj_b, fc_w, fc_b, out);
}

// round 6
// speedup vs baseline: 3.7393x; 1.7854x over previous
#include <cuda_runtime.h>
#include <cstdint>

// ---------------- scratch (static device globals; no allocations) ----------
__device__ float g_h1p[32u*64*66*66];    // conv1 out, padded NCHW [32][64][66][66]
__device__ float g_w2f[9*8192];          // conv2 weights, mma-fragment order (tf32)
__device__ float g_wqkv[24576];          // qkv weights [192 x 128], fragment order (tf32, q pre-scaled)
__device__ float g_f [32u*32*32*128];    // conv2 out, NHWC, tf32-rounded values
__device__ float g_fpart[1024*128];      // per-(b,Y) column sums of f (exact)
__device__ float g_q [32u*4*1024*16];    // [b,head,y,x,d]
__device__ float g_k [32u*4*1024*16];
__device__ float g_v [32u*4*1024*16];
__device__ float g_osum[128*16];         // per-(b,head) sum over tokens of (o_row+o_col)

// ---------------- helpers ----------------------------------------------------
__device__ __forceinline__ uint32_t smem_u32(const void* p) {
    uint32_t a;
    asm("{ .reg .u64 t; cvta.to.shared.u64 t, %1; cvt.u32.u64 %0, t; }"
        : "=r"(a) : "l"(p));
    return a;
}
__device__ __forceinline__ float tf32r(float x) {
    uint32_t u;
    asm("cvt.rna.tf32.f32 %0, %1;" : "=r"(u) : "f"(x));
    return __uint_as_float(u);
}
__device__ __forceinline__ void cpa16(uint32_t d, const void* s) {
    asm volatile("cp.async.cg.shared.global [%0], [%1], 16;" :: "r"(d), "l"(s));
}
__device__ __forceinline__ void cpa8(uint32_t d, const void* s) {
    asm volatile("cp.async.ca.shared.global [%0], [%1], 8;" :: "r"(d), "l"(s));
}
__device__ __forceinline__ void mma16n8k8(float* c, const uint32_t* a, const uint32_t* b) {
    asm volatile("mma.sync.aligned.m16n8k8.row.col.f32.tf32.tf32.f32 "
        "{%0,%1,%2,%3}, {%4,%5,%6,%7}, {%8,%9}, {%0,%1,%2,%3};"
        : "+f"(c[0]), "+f"(c[1]), "+f"(c[2]), "+f"(c[3])
        : "r"(a[0]), "r"(a[1]), "r"(a[2]), "r"(a[3]), "r"(b[0]), "r"(b[1]));
}
__device__ __forceinline__ float dot16(float4 q0, float4 q1, float4 q2, float4 q3,
                                       const float4* kp) {
    float4 k0 = kp[0], k1 = kp[1], k2 = kp[2], k3 = kp[3];
    float s = q0.x*k0.x;
    s = fmaf(q0.y, k0.y, s); s = fmaf(q0.z, k0.z, s); s = fmaf(q0.w, k0.w, s);
    s = fmaf(q1.x, k1.x, s); s = fmaf(q1.y, k1.y, s); s = fmaf(q1.z, k1.z, s); s = fmaf(q1.w, k1.w, s);
    s = fmaf(q2.x, k2.x, s); s = fmaf(q2.y, k2.y, s); s = fmaf(q2.z, k2.z, s); s = fmaf(q2.w, k2.w, s);
    s = fmaf(q3.x, k3.x, s); s = fmaf(q3.y, k3.y, s); s = fmaf(q3.z, k3.z, s); s = fmaf(q3.w, k3.w, s);
    return s;
}

// ---------------- border zero for padded NCHW h1 ----------------------------
__global__ __launch_bounds__(256) void zero_border_kernel() {
    int b = blockIdx.x;
    float* hb = g_h1p + (size_t)b * 64 * 4356;
    for (int i = threadIdx.x; i < 16640; i += 256) {
        int co = i / 260, j = i % 260;
        int p, q;
        if (j < 66)       { p = 0;          q = j; }
        else if (j < 132) { p = 65;         q = j - 66; }
        else if (j < 196) { p = j - 132 + 1; q = 0; }
        else              { p = j - 196 + 1; q = 65; }
        hb[(size_t)co * 4356 + p * 66 + q] = 0.f;
    }
}

// ---------------- conv2 weight prep: [co][ci][t] -> fragment order ----------
__global__ __launch_bounds__(256) void w2f_kernel(const float* __restrict__ w2) {
    int i = blockIdx.x * 256 + threadIdx.x;
    if (i < 73728) {
        int t = i / 8192;
        int r = i - t * 8192;
        int z = r & 1;
        int lane = (r >> 1) & 31;
        int idx2 = r >> 6;
        int nf = idx2 & 15, ks = idx2 >> 4;
        int co = nf * 8 + (lane >> 2);
        int ci = ks * 8 + (lane & 3) + 4 * z;
        g_w2f[i] = tf32r(w2[(co * 64 + ci) * 9 + t]);
    }
}

// ---------------- qkv weight prep: fragment order, q pre-scaled by 0.25 -----
__global__ __launch_bounds__(256) void wqkv_kernel(const float* __restrict__ qw,
                                                   const float* __restrict__ kw,
                                                   const float* __restrict__ vw) {
    int i = blockIdx.x * 256 + threadIdx.x;
    if (i < 24576) {
        int z = i & 1;
        int lane = (i >> 1) & 31;
        int rest = i >> 6;
        int nf = rest % 24, ks = rest / 24;
        int o = nf * 8 + (lane >> 2);
        int k = ks * 8 + (lane & 3) + 4 * z;
        float v;
        if (o < 64)       v = qw[o*128 + k] * 0.25f;
        else if (o < 128) v = kw[(o-64)*128 + k];
        else              v = vw[(o-128)*128 + k];
        g_wqkv[i] = tf32r(v);
    }
}

// ---------------- conv1 + relu + maxpool2 -> padded NCHW (tf32-rounded) -----
__global__ __launch_bounds__(256) void conv1_kernel(const float* __restrict__ x,
                                                    const float* __restrict__ w,
                                                    const float* __restrict__ bias) {
    __shared__ float s_in[3*34*34];
    __shared__ float s_w[64*27];
    __shared__ float s_b[64];
    int b  = blockIdx.y;
    int tY = blockIdx.x >> 2, tX = blockIdx.x & 3;
    int Py0 = tY*16, Px0 = tX*16;
    int tid = threadIdx.x;

    for (int i = tid; i < 64*27; i += 256) s_w[i] = w[i];
    if (tid < 64) s_b[tid] = bias[tid];

    const float* xb = x + (size_t)b*3*128*128;
    for (int i = tid; i < 3*34*34; i += 256) {
        int ci = i / 1156, rem2 = i % 1156;
        int ly = rem2 / 34, lx = rem2 % 34;
        int gy = 2*Py0 - 1 + ly, gx = 2*Px0 - 1 + lx;
        float v = 0.f;
        if (gy >= 0 && gy < 128 && gx >= 0 && gx < 128)
            v = xb[(size_t)ci*16384 + gy*128 + gx];
        s_in[i] = v;
    }
    __syncthreads();

    int ty = tid >> 4, tx = tid & 15;
    float win[3][16];
    #pragma unroll
    for (int ci = 0; ci < 3; ci++)
        #pragma unroll
        for (int r = 0; r < 4; r++)
            #pragma unroll
            for (int c = 0; c < 4; c++)
                win[ci][r*4+c] = s_in[ci*1156 + (2*ty + r)*34 + (2*tx + c)];

    int Y = Py0 + ty, X = Px0 + tx;
    float* outp = g_h1p + (size_t)b*64*4356 + (size_t)(Y+1)*66 + (X+1);
    #pragma unroll 1
    for (int co = 0; co < 64; co++) {
        float a0=0.f, a1=0.f, a2=0.f, a3=0.f;
        const float* wp = &s_w[co*27];
        #pragma unroll
        for (int ci = 0; ci < 3; ci++)
            #pragma unroll
            for (int k = 0; k < 9; k++) {
                int ky = k/3, kx = k%3;
                float wv = wp[ci*9+k];
                a0 = fmaf(win[ci][ ky   *4 + kx    ], wv, a0);
                a1 = fmaf(win[ci][ ky   *4 + kx + 1], wv, a1);
                a2 = fmaf(win[ci][(ky+1)*4 + kx    ], wv, a2);
                a3 = fmaf(win[ci][(ky+1)*4 + kx + 1], wv, a3);
            }
        float m = fmaxf(fmaxf(a0,a1), fmaxf(a2,a3));
        outp[(size_t)co*4356] = tf32r(fmaxf(m + s_b[co], 0.f));
    }
}

// ---------------- conv2 via mma.sync tf32 (implicit GEMM, 9 taps) -----------
// Epilogue: maxpool+bias+relu, tf32-rounded store to g_f, exact column sums
// to g_fpart[bY][128].
__global__ __launch_bounds__(256) void conv2_mma_kernel(const float* __restrict__ b2) {
    extern __shared__ float sm[];
    const int tid = threadIdx.x;
    const int lane = tid & 31, wid = tid >> 5;
    const int warp_m = wid >> 1, warp_n = wid & 1;
    const int bY = blockIdx.x;
    const int b = bY >> 5, Y = bY & 31;

    uint32_t slab_b = smem_u32(sm);

    {
        const float* sb0 = g_h1p + (size_t)b*278784 + 132*Y;
        for (int i = tid; i < 8448; i += 256) {
            int ci = i / 132, w2i = i - ci*132;
            cpa8(slab_b + (uint32_t)i*8u, sb0 + (size_t)ci*4356 + w2i*2);
        }
        uint32_t bst0 = slab_b + 16896u*4u;
        for (int i = tid; i < 2048; i += 256)
            cpa16(bst0 + (uint32_t)i*16u, g_w2f + i*4);
        asm volatile("cp.async.commit_group;" ::: "memory");
    }

    float c[2][8][4];
    #pragma unroll
    for (int mf = 0; mf < 2; mf++)
        #pragma unroll
        for (int nf = 0; nf < 8; nf++)
            #pragma unroll
            for (int r = 0; r < 4; r++) c[mf][nf][r] = 0.f;

    const int ry  = warp_m >> 1;
    const int xw0 = (warp_m & 1) * 32;

    #pragma unroll 1
    for (int t = 0; t < 9; t++) {
        asm volatile("cp.async.wait_group 0;" ::: "memory");
        __syncthreads();
        if (t < 8) {
            uint32_t bstn = slab_b + (16896u + (uint32_t)((t+1)&1)*8192u)*4u;
            const float* wsrc = g_w2f + (t+1)*8192;
            for (int i = tid; i < 2048; i += 256)
                cpa16(bstn + (uint32_t)i*16u, wsrc + i*4);
            asm volatile("cp.async.commit_group;" ::: "memory");
        }
        const int ky = t / 3, kx = t - ky*3;
        const float* Abase = sm + (ry + ky)*66 + kx + xw0 + (lane >> 2) + (lane & 3)*264;
        const float* Bbase = sm + 16896 + (t & 1)*8192 + warp_n*512 + lane*2;
        #pragma unroll
        for (int ks = 0; ks < 8; ks++) {
            const float* Ak = Abase + ks*2112;
            uint32_t a[2][4];
            #pragma unroll
            for (int mf = 0; mf < 2; mf++) {
                const float* Am = Ak + mf*16;
                a[mf][0] = __float_as_uint(Am[0]);
                a[mf][1] = __float_as_uint(Am[8]);
                a[mf][2] = __float_as_uint(Am[1056]);
                a[mf][3] = __float_as_uint(Am[1064]);
            }
            const float* Bk = Bbase + ks*1024;
            uint32_t bb[8][2];
            #pragma unroll
            for (int nf = 0; nf < 8; nf++) {
                float2 v = *reinterpret_cast<const float2*>(Bk + nf*64);
                bb[nf][0] = __float_as_uint(v.x);
                bb[nf][1] = __float_as_uint(v.y);
            }
            #pragma unroll
            for (int mf = 0; mf < 2; mf++)
                #pragma unroll
                for (int nf = 0; nf < 8; nf++)
                    mma16n8k8(c[mf][nf], a[mf], bb[nf]);
        }
    }

    __syncthreads();
    #pragma unroll
    for (int mf = 0; mf < 2; mf++)
        #pragma unroll
        for (int nf = 0; nf < 8; nf++) {
            int m0 = warp_m*32 + mf*16 + (lane >> 2);
            int n0 = warp_n*64 + nf*8 + (lane & 3)*2;
            *reinterpret_cast<float2*>(sm + m0*132 + n0)     = make_float2(c[mf][nf][0], c[mf][nf][1]);
            *reinterpret_cast<float2*>(sm + (m0+8)*132 + n0) = make_float2(c[mf][nf][2], c[mf][nf][3]);
        }
    __syncthreads();
    float* gf = g_f + (((size_t)b*32 + Y)*32)*128;
    float fsum = 0.f;
    #pragma unroll
    for (int u = 0; u < 16; u++) {
        int idx = tid + u*256;
        int cch = idx & 127, xo = idx >> 7;
        float v0 = fmaxf(sm[(2*xo)*132 + cch],    sm[(2*xo+1)*132 + cch]);
        float v1 = fmaxf(sm[(64+2*xo)*132 + cch], sm[(64+2*xo+1)*132 + cch]);
        float v = fmaxf(fmaxf(v0, v1) + __ldg(&b2[cch]), 0.f);
        fsum += v;
        gf[(size_t)xo*128 + cch] = tf32r(v);
    }
    float* red = sm + 20480;   // B region, free after mma
    red[tid] = fsum;
    __syncthreads();
    if (tid < 128) g_fpart[(size_t)bY*128 + tid] = red[tid] + red[tid+128];
}

// ---------------- qkv via mma.sync tf32: [32768,128] x [192,128]^T ----------
// CTA = 128 tokens. A tile (tf32 g_f) 128x132 pad; full B (24576 floats) in smem.
// 8 warps: warp_m in 0..3 (32 tokens), warp_n in 0..1 (96 outputs = 12 nf).
__global__ __launch_bounds__(256) void qkv_mma_kernel(
    const float* __restrict__ qb, const float* __restrict__ kb,
    const float* __restrict__ vb) {
    extern __shared__ float sm[];
    const int tid = threadIdx.x;
    const int lane = tid & 31, wid = tid >> 5;
    const int warp_m = wid >> 1, warp_n = wid & 1;
    uint32_t smb = smem_u32(sm);

    {
        const float* gf0 = g_f + (size_t)blockIdx.x*16384;
        for (int i = tid; i < 4096; i += 256) {
            int row = i >> 5, cg = i & 31;
            cpa16(smb + (uint32_t)(row*132 + cg*4)*4u, gf0 + i*4);
        }
        uint32_t bsb = smb + 16896u*4u;
        for (int i = tid; i < 6144; i += 256)
            cpa16(bsb + (uint32_t)i*16u, g_wqkv + i*4);
        asm volatile("cp.async.commit_group;" ::: "memory");
        asm volatile("cp.async.wait_group 0;" ::: "memory");
    }
    __syncthreads();

    float c[2][12][4];
    #pragma unroll
    for (int mf = 0; mf < 2; mf++)
        #pragma unroll
        for (int nf = 0; nf < 12; nf++)
            #pragma unroll
            for (int r = 0; r < 4; r++) c[mf][nf][r] = 0.f;

    const float* Ab = sm + (warp_m*32 + (lane >> 2))*132 + (lane & 3);
    const float* Bb = sm + 16896 + (warp_n*12*64) + lane*2;

    #pragma unroll 1
    for (int ks = 0; ks < 16; ks++) {
        uint32_t a[2][4];
        const float* Ak = Ab + ks*8;
        #pragma unroll
        for (int mf = 0; mf < 2; mf++) {
            const float* Am = Ak + mf*2112;
            a[mf][0] = __float_as_uint(Am[0]);
            a[mf][1] = __float_as_uint(Am[1056]);
            a[mf][2] = __float_as_uint(Am[4]);
            a[mf][3] = __float_as_uint(Am[1060]);
        }
        const float* Bk = Bb + ks*1536;
        uint32_t bb[12][2];
        #pragma unroll
        for (int nf = 0; nf < 12; nf++) {
            float2 v = *reinterpret_cast<const float2*>(Bk + nf*64);
            bb[nf][0] = __float_as_uint(v.x);
            bb[nf][1] = __float_as_uint(v.y);
        }
        #pragma unroll
        for (int mf = 0; mf < 2; mf++)
            #pragma unroll
            for (int nf = 0; nf < 12; nf++)
                mma16n8k8(c[mf][nf], a[mf], bb[nf]);
    }

    // epilogue: direct stores (32B contiguous per 8-lane group within a head)
    const int bb_  = blockIdx.x >> 3;
    const int rem0 = (blockIdx.x & 7)*128 + warp_m*32 + (lane >> 2);
    const int opair = (lane & 3)*2;
    #pragma unroll
    for (int nf = 0; nf < 12; nf++) {
        int o = warp_n*96 + nf*8 + opair;
        float b0, b1; float* basep; int oo;
        if (o < 64)       { b0 = __ldg(&qb[o])*0.25f;   b1 = __ldg(&qb[o+1])*0.25f;   basep = g_q; oo = o; }
        else if (o < 128) { b0 = __ldg(&kb[o-64]);      b1 = __ldg(&kb[o-63]);        basep = g_k; oo = o-64; }
        else              { b0 = __ldg(&vb[o-128]);     b1 = __ldg(&vb[o-127]);       basep = g_v; oo = o-128; }
        int head = oo >> 4, d = oo & 15;
        float* hb = basep + ((size_t)(bb_*4 + head)*1024)*16 + d;
        #pragma unroll
        for (int mf = 0; mf < 2; mf++) {
            int rem = rem0 + mf*16;
            *reinterpret_cast<float2*>(hb + (size_t)rem*16)
                = make_float2(c[mf][nf][0] + b0, c[mf][nf][1] + b1);
            *reinterpret_cast<float2*>(hb + (size_t)(rem + 8)*16)
                = make_float2(c[mf][nf][2] + b0, c[mf][nf][3] + b1);
        }
    }
}

// ---------------- fused axial attention (row + col), one CTA per (b,head) ---
// No o materialization: accumulates sum_t(o_row+o_col) -> g_osum[bh][16].
__global__ __launch_bounds__(256) void attn_fused_kernel(const float* __restrict__ rel_w,
                                                         const float* __restrict__ rel_h) {
    extern __shared__ float asmem[];
    float* ks  = asmem;            // 16384
    float* vs  = asmem + 16384;    // 16384
    float* srw = asmem + 32768;    // 64
    float* srh = asmem + 32832;    // 64
    const int bh = blockIdx.x;
    const int head = bh & 3;
    const int tid = threadIdx.x;
    const int l = tid & 31, w = tid >> 5;

    {
        const float4* gk = (const float4*)(g_k + (size_t)bh*16384);
        const float4* gv = (const float4*)(g_v + (size_t)bh*16384);
        float4* k4 = (float4*)ks;
        float4* v4 = (float4*)vs;
        for (int i = tid; i < 4096; i += 256) { k4[i] = gk[i]; v4[i] = gv[i]; }
        if (tid < 63) { srw[tid] = rel_w[head*63 + tid]; srh[tid] = rel_h[head*63 + tid]; }
    }
    __syncthreads();

    const float* gq = g_q + (size_t)bh*16384;
    float4 acc0 = {0,0,0,0}, acc1 = {0,0,0,0}, acc2 = {0,0,0,0}, acc3 = {0,0,0,0};

    // ---- phase 1: rows; token t = y*32 + l, y = w + 8u ----
    #pragma unroll 1
    for (int u = 0; u < 4; u++) {
        const int y = w + 8*u;
        const int t = y*32 + l;
        const float4* qp = (const float4*)(gq + t*16);
        const float4 q0 = qp[0], q1 = qp[1], q2 = qp[2], q3 = qp[3];
        float sc[32];
        float mx = -1e30f;
        #pragma unroll
        for (int j = 0; j < 32; j++) {
            float s = dot16(q0, q1, q2, q3, (const float4*)(ks + (y*32 + j)*16));
            s += srw[l - j + 31];
            sc[j] = s;
            mx = fmaxf(mx, s);
        }
        float ssum = 0.f;
        #pragma unroll
        for (int j = 0; j < 32; j++) { sc[j] = __expf(sc[j] - mx); ssum += sc[j]; }
        const float inv = 1.f / ssum;
        float4 o0 = {0,0,0,0}, o1 = {0,0,0,0}, o2 = {0,0,0,0}, o3 = {0,0,0,0};
        #pragma unroll
        for (int j = 0; j < 32; j++) {
            const float4* vp = (const float4*)(vs + (y*32 + j)*16);
            const float p = sc[j];
            float4 v0 = vp[0], v1 = vp[1], v2 = vp[2], v3 = vp[3];
            o0.x = fmaf(p, v0.x, o0.x); o0.y = fmaf(p, v0.y, o0.y);
            o0.z = fmaf(p, v0.z, o0.z); o0.w = fmaf(p, v0.w, o0.w);
            o1.x = fmaf(p, v1.x, o1.x); o1.y = fmaf(p, v1.y, o1.y);
            o1.z = fmaf(p, v1.z, o1.z); o1.w = fmaf(p, v1.w, o1.w);
            o2.x = fmaf(p, v2.x, o2.x); o2.y = fmaf(p, v2.y, o2.y);
            o2.z = fmaf(p, v2.z, o2.z); o2.w = fmaf(p, v2.w, o2.w);
            o3.x = fmaf(p, v3.x, o3.x); o3.y = fmaf(p, v3.y, o3.y);
            o3.z = fmaf(p, v3.z, o3.z); o3.w = fmaf(p, v3.w, o3.w);
        }
        acc0.x = fmaf(o0.x, inv, acc0.x); acc0.y = fmaf(o0.y, inv, acc0.y);
        acc0.z = fmaf(o0.z, inv, acc0.z); acc0.w = fmaf(o0.w, inv, acc0.w);
        acc1.x = fmaf(o1.x, inv, acc1.x); acc1.y = fmaf(o1.y, inv, acc1.y);
        acc1.z = fmaf(o1.z, inv, acc1.z); acc1.w = fmaf(o1.w, inv, acc1.w);
        acc2.x = fmaf(o2.x, inv, acc2.x); acc2.y = fmaf(o2.y, inv, acc2.y);
        acc2.z = fmaf(o2.z, inv, acc2.z); acc2.w = fmaf(o2.w, inv, acc2.w);
        acc3.x = fmaf(o3.x, inv, acc3.x); acc3.y = fmaf(o3.y, inv, acc3.y);
        acc3.z = fmaf(o3.z, inv, acc3.z); acc3.w = fmaf(o3.w, inv, acc3.w);
    }

    // ---- phase 2: cols; token t = l*32 + x, x = w + 8u ----
    #pragma unroll 1
    for (int u = 0; u < 4; u++) {
        const int x = w + 8*u;
        const int t = l*32 + x;
        const float4* qp = (const float4*)(gq + t*16);
        const float4 q0 = qp[0], q1 = qp[1], q2 = qp[2], q3 = qp[3];
        float sc[32];
        float mx = -1e30f;
        #pragma unroll
        for (int i = 0; i < 32; i++) {
            float s = dot16(q0, q1, q2, q3, (const float4*)(ks + (i*32 + x)*16));
            s += srh[l - i + 31];
            sc[i] = s;
            mx = fmaxf(mx, s);
        }
        float ssum = 0.f;
        #pragma unroll
        for (int i = 0; i < 32; i++) { sc[i] = __expf(sc[i] - mx); ssum += sc[i]; }
        const float inv = 1.f / ssum;
        float4 o0 = {0,0,0,0}, o1 = {0,0,0,0}, o2 = {0,0,0,0}, o3 = {0,0,0,0};
        #pragma unroll
        for (int i = 0; i < 32; i++) {
            const float4* vp = (const float4*)(vs + (i*32 + x)*16);
            const float p = sc[i];
            float4 v0 = vp[0], v1 = vp[1], v2 = vp[2], v3 = vp[3];
            o0.x = fmaf(p, v0.x, o0.x); o0.y = fmaf(p, v0.y, o0.y);
            o0.z = fmaf(p, v0.z, o0.z); o0.w = fmaf(p, v0.w, o0.w);
            o1.x = fmaf(p, v1.x, o1.x); o1.y = fmaf(p, v1.y, o1.y);
            o1.z = fmaf(p, v1.z, o1.z); o1.w = fmaf(p, v1.w, o1.w);
            o2.x = fmaf(p, v2.x, o2.x); o2.y = fmaf(p, v2.y, o2.y);
            o2.z = fmaf(p, v2.z, o2.z); o2.w = fmaf(p, v2.w, o2.w);
            o3.x = fmaf(p, v3.x, o3.x); o3.y = fmaf(p, v3.y, o3.y);
            o3.z = fmaf(p, v3.z, o3.z); o3.w = fmaf(p, v3.w, o3.w);
        }
        acc0.x = fmaf(o0.x, inv, acc0.x); acc0.y = fmaf(o0.y, inv, acc0.y);
        acc0.z = fmaf(o0.z, inv, acc0.z); acc0.w = fmaf(o0.w, inv, acc0.w);
        acc1.x = fmaf(o1.x, inv, acc1.x); acc1.y = fmaf(o1.y, inv, acc1.y);
        acc1.z = fmaf(o1.z, inv, acc1.z); acc1.w = fmaf(o1.w, inv, acc1.w);
        acc2.x = fmaf(o2.x, inv, acc2.x); acc2.y = fmaf(o2.y, inv, acc2.y);
        acc2.z = fmaf(o2.z, inv, acc2.z); acc2.w = fmaf(o2.w, inv, acc2.w);
        acc3.x = fmaf(o3.x, inv, acc3.x); acc3.y = fmaf(o3.y, inv, acc3.y);
        acc3.z = fmaf(o3.z, inv, acc3.z); acc3.w = fmaf(o3.w, inv, acc3.w);
    }

    // ---- block-reduce 256 x 16 -> g_osum[bh][16] ----
    __syncthreads();                 // done reading ks/vs
    float* red = asmem;              // stride 20 floats (16B-aligned, 4-way max)
    float4* r4 = (float4*)(red + tid*20);
    r4[0] = acc0; r4[1] = acc1; r4[2] = acc2; r4[3] = acc3;
    __syncthreads();
    #pragma unroll
    for (int s = 128; s > 0; s >>= 1) {
        if (tid < s) {
            float* a_ = red + tid*20;
            const float* b_ = red + (tid + s)*20;
            #pragma unroll
            for (int d = 0; d < 16; d++) a_[d] += b_[d];
        }
        __syncthreads();
    }
    if (tid < 16) g_osum[bh*16 + tid] = red[tid];
}

// ---------------- final: tiny GEMV from partial sums ------------------------
__global__ __launch_bounds__(128) void reduce_kernel(
    const float* __restrict__ proj_w, const float* __restrict__ proj_b,
    const float* __restrict__ fc_w,   const float* __restrict__ fc_b,
    float* __restrict__ out) {
    int b = blockIdx.x, tid = threadIdx.x;
    __shared__ float meano[64], pooled[128];
    if (tid < 64) meano[tid] = g_osum[b*64 + tid] * (1.f/1024.f);
    float s = 0.f;
    #pragma unroll 4
    for (int Y = 0; Y < 32; Y++) s += g_fpart[(size_t)(b*32 + Y)*128 + tid];
    float pv = s * (1.f/1024.f) + proj_b[tid];
    __syncthreads();
    #pragma unroll 8
    for (int d = 0; d < 64; d++) pv = fmaf(proj_w[tid*64 + d], meano[d], pv);
    pooled[tid] = pv;
    __syncthreads();
    if (tid < 10) {
        float v2 = fc_b[tid];
        #pragma unroll 8
        for (int cc = 0; cc < 128; cc++) v2 = fmaf(fc_w[tid*128 + cc], pooled[cc], v2);
        out[b*10 + tid] = v2;
    }
}

// ---------------- launch ----------------------------------------------------
extern "C" void kernel_launch(void* const* d_in, const int* in_sizes, int n_in,
                              void* d_out, int out_size) {
    (void)in_sizes; (void)n_in; (void)out_size;
    const float* x       = (const float*)d_in[0];
    const float* conv1_w = (const float*)d_in[1];
    const float* conv1_b = (const float*)d_in[2];
    const float* conv2_w = (const float*)d_in[3];
    const float* conv2_b = (const float*)d_in[4];
    const float* q_w     = (const float*)d_in[5];
    const float* q_b     = (const float*)d_in[6];
    const float* k_w     = (const float*)d_in[7];
    const float* k_b     = (const float*)d_in[8];
    const float* v_w     = (const float*)d_in[9];
    const float* v_b     = (const float*)d_in[10];
    const float* proj_w  = (const float*)d_in[11];
    const float* proj_b  = (const float*)d_in[12];
    const float* rel_h   = (const float*)d_in[13];
    const float* rel_w   = (const float*)d_in[14];
    const float* fc_w    = (const float*)d_in[15];
    const float* fc_b    = (const float*)d_in[16];
    float* out = (float*)d_out;

    const int CONV2_SMEM = 33280 * 4;          // 133120 B
    const int QKV_SMEM   = (16896 + 24576) * 4; // 165888 B
    const int ATTN_SMEM  = (32768 + 128) * 4;  // 131584 B
    cudaFuncSetAttribute(conv2_mma_kernel, cudaFuncAttributeMaxDynamicSharedMemorySize, CONV2_SMEM);
    cudaFuncSetAttribute(qkv_mma_kernel,  cudaFuncAttributeMaxDynamicSharedMemorySize, QKV_SMEM);
    cudaFuncSetAttribute(attn_fused_kernel, cudaFuncAttributeMaxDynamicSharedMemorySize, ATTN_SMEM);

    zero_border_kernel<<<32, 256>>>();
    w2f_kernel<<<288, 256>>>(conv2_w);
    wqkv_kernel<<<96, 256>>>(q_w, k_w, v_w);
    conv1_kernel<<<dim3(16,32), 256>>>(x, conv1_w, conv1_b);
    conv2_mma_kernel<<<1024, 256, CONV2_SMEM>>>(conv2_b);
    qkv_mma_kernel<<<256, 256, QKV_SMEM>>>(q_b, k_b, v_b);
    attn_fused_kernel<<<128, 256, ATTN_SMEM>>>(rel_w, rel_h);
    reduce_kernel<<<32, 128>>>(proj_w, proj_b, fc_w, fc_b, out);
}